// round 15
// baseline (speedup 1.0000x reference)
#include <cuda_runtime.h>
#include <cuda_bf16.h>
#include <cuda_fp16.h>
#include <math.h>
#include <cstdint>

#define Bb 2
#define Ss 2048
#define Ee 2048
#define Hh 16
#define Dh 128
#define GK 2048          // fp16 single-pass: K = E
#define GKC64 32         // GK / 64 chunks

#define GSTAGE_BYTES 36864                      // (A 128 + B 128 rows) * 144 B
#define GEMM_SMEM_BYTES (3 * GSTAGE_BYTES)      // 110592 -> 2 CTAs/SM

// ---------------- scratch (__device__ globals; no allocation allowed) -------
__device__ __half g_a_p[(size_t)Bb * Ss * GK];        // fp16 activations
__device__ __half g_wqkv_p[(size_t)3 * Ee * GK];      // fp16 Wqkv
__device__ __half g_wout_p[(size_t)Ee * GK];          // fp16 Wout
__device__ __half g_qp[(size_t)Bb * Hh * Ss * Dh];    // q fp16, roped, scale*log2e
__device__ __half g_kp[(size_t)Bb * Hh * Ss * Dh];    // k fp16, roped
__device__ __half g_vt[(size_t)Bb * Hh * Dh * Ss];    // V^T fp16
__device__ float g_rope[(size_t)Ss * 16 * 2];         // (cos,sin) per (s, i)

__device__ __forceinline__ uint32_t smem_u32(const void* p) {
    uint32_t a;
    asm("{ .reg .u64 t; cvta.to.shared.u64 t, %1; cvt.u32.u64 %0, t; }"
        : "=r"(a) : "l"(p));
    return a;
}

// ---------------------------------------------------------------------------
// Fused prep kernel: blocks [0,1536) pack Wqkv (fp32->fp16, x8),
// blocks [1536,2560) pack hidden, blocks [2560,2688) build the rope table.
// ---------------------------------------------------------------------------
__global__ __launch_bounds__(256) void pack_all(
    const float* __restrict__ wqkv, const float* __restrict__ hidden)
{
    const int bid = blockIdx.x;
    if (bid < 1536) {
        int i0 = bid * 2048 + threadIdx.x;
#pragma unroll
        for (int t = 0; t < 8; t++) {
            int i = i0 + t * 256;
            float4 x = *(const float4*)(wqkv + (size_t)i * 4);
            *(__half2*)(g_wqkv_p + (size_t)i * 4) = __floats2half2_rn(x.x, x.y);
            *(__half2*)(g_wqkv_p + (size_t)i * 4 + 2) = __floats2half2_rn(x.z, x.w);
        }
    } else if (bid < 2560) {
        int i0 = (bid - 1536) * 2048 + threadIdx.x;
#pragma unroll
        for (int t = 0; t < 8; t++) {
            int i = i0 + t * 256;
            float4 x = *(const float4*)(hidden + (size_t)i * 4);
            *(__half2*)(g_a_p + (size_t)i * 4) = __floats2half2_rn(x.x, x.y);
            *(__half2*)(g_a_p + (size_t)i * 4 + 2) = __floats2half2_rn(x.z, x.w);
        }
    } else {
        int idx = (bid - 2560) * 256 + threadIdx.x;   // Ss*16 entries
        int i = idx & 15, s = idx >> 4;
        float f = powf(10000.f, -(float)i * 0.0625f);
        float sn, cs;
        sincosf((float)s * f, &sn, &cs);
        *(float2*)&g_rope[(size_t)idx * 2] = make_float2(cs, sn);
    }
}

// ---------------------------------------------------------------------------
// mma helpers
// ---------------------------------------------------------------------------
__device__ __forceinline__ void mma_fp16(float* c, const uint32_t* a, const uint32_t* b) {
    asm volatile(
        "mma.sync.aligned.m16n8k16.row.col.f32.f16.f16.f32 "
        "{%0,%1,%2,%3}, {%4,%5,%6,%7}, {%8,%9}, {%0,%1,%2,%3};"
        : "+f"(c[0]), "+f"(c[1]), "+f"(c[2]), "+f"(c[3])
        : "r"(a[0]), "r"(a[1]), "r"(a[2]), "r"(a[3]), "r"(b[0]), "r"(b[1]));
}
__device__ __forceinline__ void ldsm_x4(uint32_t* r, uint32_t addr) {
    asm volatile("ldmatrix.sync.aligned.m8n8.x4.shared.b16 {%0,%1,%2,%3}, [%4];"
        : "=r"(r[0]), "=r"(r[1]), "=r"(r[2]), "=r"(r[3]) : "r"(addr));
}
__device__ __forceinline__ uint32_t ex2_f16x2(uint32_t x) {
    uint32_t r;
    asm volatile("ex2.approx.f16x2 %0, %1;" : "=r"(r) : "r"(x));
    return r;
}

// ---------------------------------------------------------------------------
// fp16 GEMM (frozen shape): CTA 128x128, 8 warps (2M x 4N), warp 64x32,
// 256 threads, 2 CTAs/SM.  K-chunk 64, 3-stage cp.async, 144 B pitch.
// MODE 0: fp32 store.  MODE 1: QKV epilogue (rope table + fp16 q/k/v^T).
// ---------------------------------------------------------------------------
template <int MODE>
__global__ __launch_bounds__(256, 2) void gemm_mma(
    const __half* __restrict__ A, const __half* __restrict__ Bw,
    float* __restrict__ C, int Ncols)
{
    extern __shared__ __align__(16) uint32_t gsm[];
    const uint32_t sbase = smem_u32(gsm);

    const int tid = threadIdx.x;
    const int lane = tid & 31, w = tid >> 5;
    const int wm = w & 1, wn = w >> 1;
    const int mbase = blockIdx.y * 128, nbase = blockIdx.x * 128;

    float acc[4][4][4];
#pragma unroll
    for (int i = 0; i < 4; i++)
#pragma unroll
        for (int j = 0; j < 4; j++)
#pragma unroll
            for (int r = 0; r < 4; r++) acc[i][j][r] = 0.f;

    const int grow = tid >> 3, gseg = tid & 7;
    const __half* Ag = A + (size_t)(mbase + grow) * GK + gseg * 8;
    const __half* Bg = Bw + (size_t)(nbase + grow) * GK + gseg * 8;
    const size_t rstep32 = (size_t)32 * GK;
    const uint32_t dbase = grow * 144 + gseg * 16;

#define ISSUE(c, str) do {                                                     \
    uint32_t st = sbase + (uint32_t)(str) * GSTAGE_BYTES;                      \
    const __half* sA = Ag + (size_t)(c) * 64;                                  \
    const __half* sB = Bg + (size_t)(c) * 64;                                  \
    _Pragma("unroll")                                                          \
    for (int j = 0; j < 4; j++) {                                              \
        asm volatile("cp.async.cg.shared.global [%0], [%1], 16;"               \
            :: "r"(st + dbase + j * (32 * 144)), "l"(sA + j * rstep32));       \
        asm volatile("cp.async.cg.shared.global [%0], [%1], 16;"               \
            :: "r"(st + 18432 + dbase + j * (32 * 144)), "l"(sB + j * rstep32)); \
    }                                                                          \
} while (0)
#define COMMIT() asm volatile("cp.async.commit_group;" ::: "memory")
#define WAITG1() asm volatile("cp.async.wait_group 1;" ::: "memory")

    ISSUE(0, 0); COMMIT();
    ISSUE(1, 1); COMMIT();

    const int lane8 = lane & 7;
    const uint32_t aAddr = (uint32_t)((wm * 64 + ((lane >> 3) & 1) * 8 + lane8) * 144
                                      + (lane >> 4) * 16);
    const uint32_t bAddr = (uint32_t)(18432 + (wn * 32 + (lane >> 4) * 8 + lane8) * 144
                                      + ((lane >> 3) & 1) * 16);

    int str = 2, srd = 0;
    for (int c = 0; c < GKC64; c++) {
        WAITG1();
        __syncthreads();
        if (c + 2 < GKC64) ISSUE(c + 2, str);
        COMMIT();
        if (++str == 3) str = 0;

        const uint32_t st = sbase + (uint32_t)srd * GSTAGE_BYTES;
        if (++srd == 3) srd = 0;
#pragma unroll
        for (int ks = 0; ks < 4; ks++) {
            uint32_t a[4][4], b[2][4];
#pragma unroll
            for (int i = 0; i < 4; i++)
                ldsm_x4(a[i], st + aAddr + i * (16 * 144) + ks * 32);
#pragma unroll
            for (int jp = 0; jp < 2; jp++)
                ldsm_x4(b[jp], st + bAddr + jp * (16 * 144) + ks * 32);
#pragma unroll
            for (int i = 0; i < 4; i++)
#pragma unroll
                for (int j = 0; j < 4; j++)
                    mma_fp16(acc[i][j], a[i], &b[j >> 1][(j & 1) * 2]);
        }
    }

#pragma unroll
    for (int i = 0; i < 4; i++) {
        int m0 = mbase + wm * 64 + i * 16 + (lane >> 2);
#pragma unroll
        for (int j = 0; j < 4; j++) {
            int n0 = nbase + wn * 32 + j * 8 + (lane & 3) * 2;
            if constexpr (MODE == 0) {
                *(float2*)(C + (size_t)m0 * Ncols + n0) =
                    make_float2(acc[i][j][0], acc[i][j][1]);
                *(float2*)(C + (size_t)(m0 + 8) * Ncols + n0) =
                    make_float2(acc[i][j][2], acc[i][j][3]);
            } else {
                int mp = n0 / 768;
                int rr = n0 - mp * 768;
                int which = rr >> 8;
                int ccc = rr & 255;
                int hh = mp * 2 + (ccc >> 7);
                int dd = ccc & 127;
                int bb = m0 >> 11, ss = m0 & 2047;
                int bh2 = bb * Hh + hh;
                float v0 = acc[i][j][0], v1 = acc[i][j][1];
                float v2 = acc[i][j][2], v3 = acc[i][j][3];
                if (which == 2) {
                    size_t vb = ((size_t)bh2 * Dh + dd) * (size_t)Ss + ss;
                    g_vt[vb] = __float2half(v0);
                    g_vt[vb + Ss] = __float2half(v1);
                    g_vt[vb + 8] = __float2half(v2);
                    g_vt[vb + Ss + 8] = __float2half(v3);
                } else {
                    if (dd < 32) {
                        int ir = dd >> 1;
                        float2 cs1 = *(float2*)&g_rope[((size_t)ss * 16 + ir) * 2];
                        float2 cs2 = *(float2*)&g_rope[((size_t)(ss + 8) * 16 + ir) * 2];
                        float t0 = v0 * cs1.x - v1 * cs1.y;
                        v1 = v1 * cs1.x + v0 * cs1.y; v0 = t0;
                        t0 = v2 * cs2.x - v3 * cs2.y;
                        v3 = v3 * cs2.x + v2 * cs2.y; v2 = t0;
                    }
                    if (which == 0) {
                        // 1/sqrt(128) * log2(e): scores in log2 domain
                        const float sc = 0.08838834764831845f * 1.4426950408889634f;
                        v0 *= sc; v1 *= sc; v2 *= sc; v3 *= sc;
                    }
                    __half* P = (which == 0) ? g_qp : g_kp;
                    size_t rb = ((size_t)bh2 * Ss + ss) * Dh + dd;
                    *(__half2*)(P + rb) = __floats2half2_rn(v0, v1);
                    *(__half2*)(P + rb + 8 * Dh) = __floats2half2_rn(v2, v3);
                }
            }
        }
    }
}

// ---------------------------------------------------------------------------
// Flash attention v9: register-resident P (FA2 fragment identity) +
// Q fragments hoisted into registers (loaded once, t==0) +
// warp-vote lazy O-rescale (skip the 32 FMULs when corr==1 for all lanes;
// x1.0 is an exact IEEE identity so results are bit-identical).
// smem: Qs 64x272 + 2x(Ks 64x272) + 2x(Vs 128x144) = 89088 B, 2 CTAs/SM.
// Wout fp32->fp16 pack fused in prologue.
// ---------------------------------------------------------------------------
#define ATTN_SMEM 89088

__global__ __launch_bounds__(128, 2) void attn9(
    const __half* __restrict__ qp, const __half* __restrict__ kp,
    const __half* __restrict__ vt, const float* __restrict__ wout_src)
{
    extern __shared__ char sm5[];
    const uint32_t sb = smem_u32(sm5);
    const uint32_t Qs = sb;              // 64*272 = 17408
    const uint32_t Ks0 = sb + 17408;     // + buf*17408 (2 bufs)
    const uint32_t Vs0 = sb + 52224;     // + buf*18432 (2 bufs)

    const int qb = (int)gridDim.x - 1 - (int)blockIdx.x;   // long blocks first
    const int h = blockIdx.y, b = blockIdx.z;
    const int bh = b * Hh + h;
    const int tid = threadIdx.x, lane = tid & 31, w = tid >> 5;
    const int qbase = qb * 64;
    const int ntiles = qb + 1;

    // Q tile: 64 rows x 128 halves
    {
        const __half* qg = qp + ((size_t)bh * Ss + qbase) * Dh;
#pragma unroll
        for (int t = 0; t < 8; t++) {
            int u = tid + t * 128;
            int r = u >> 4, sg = u & 15;
            asm volatile("cp.async.cg.shared.global [%0], [%1], 16;"
                :: "r"(Qs + r * 272 + sg * 16), "l"(qg + r * Dh + sg * 8));
        }
        asm volatile("cp.async.commit_group;" ::: "memory");
    }

#define ISSUE_T(tt, buf) do {                                                  \
    const __half* kg = kp + ((size_t)bh * Ss + (tt) * 64) * Dh;                \
    uint32_t kd = Ks0 + (buf) * 17408;                                         \
    _Pragma("unroll")                                                          \
    for (int t_ = 0; t_ < 8; t_++) {                                           \
        int u = tid + t_ * 128;                                                \
        int r = u >> 4, sg = u & 15;                                           \
        asm volatile("cp.async.cg.shared.global [%0], [%1], 16;"               \
            :: "r"(kd + r * 272 + sg * 16), "l"(kg + r * Dh + sg * 8));        \
    }                                                                          \
    const __half* vg = vt + (size_t)bh * Dh * Ss + (tt) * 64;                  \
    uint32_t vd = Vs0 + (buf) * 18432;                                         \
    _Pragma("unroll")                                                          \
    for (int t_ = 0; t_ < 8; t_++) {                                           \
        int u = tid + t_ * 128;                                                \
        int r = u >> 3, sg = u & 7;                                            \
        asm volatile("cp.async.cg.shared.global [%0], [%1], 16;"               \
            :: "r"(vd + r * 144 + sg * 16), "l"(vg + (size_t)r * Ss + sg * 8)); \
    }                                                                          \
} while (0)

    ISSUE_T(0, 0);
    asm volatile("cp.async.commit_group;" ::: "memory");
    if (ntiles > 1) ISSUE_T(1, 1);
    asm volatile("cp.async.commit_group;" ::: "memory");

    // ---- fused Wout pack: 1024 CTAs x 1024 float4 units (8 per thread).
    {
        int cta = (int)blockIdx.x + 32 * ((int)blockIdx.y + 16 * (int)blockIdx.z);
        int base = cta * 1024 + tid;
#pragma unroll
        for (int t = 0; t < 8; t++) {
            int i = base + t * 128;
            float4 x = *(const float4*)(wout_src + (size_t)i * 4);
            *(__half2*)(g_wout_p + (size_t)i * 4) = __floats2half2_rn(x.x, x.y);
            *(__half2*)(g_wout_p + (size_t)i * 4 + 2) = __floats2half2_rn(x.z, x.w);
        }
    }

    float O[16][4];
#pragma unroll
    for (int i = 0; i < 16; i++)
#pragma unroll
        for (int r = 0; r < 4; r++) O[i][r] = 0.f;
    float m[2] = {-1e30f, -1e30f}, l[2] = {0.f, 0.f};

    const uint32_t aQ = Qs + (w * 16 + (lane & 15)) * 272 + (lane >> 4) * 16;
    const int bRow = (lane >> 4) * 8 + (lane & 7);
    const int bCol = ((lane >> 3) & 1) * 16;

    uint32_t qf[8][4];   // Q fragments, loaded once at t==0

    for (int t = 0; t < ntiles; t++) {
        asm volatile("cp.async.wait_group 1;" ::: "memory");
        __syncthreads();
        if (t == 0) {
#pragma unroll
            for (int c = 0; c < 8; c++)
                ldsm_x4(qf[c], aQ + c * 32);
        }
        const int buf = t & 1;
        const uint32_t bK = Ks0 + buf * 17408 + bRow * 272 + bCol;
        const uint32_t bV = Vs0 + buf * 18432 + bRow * 144 + bCol;

        // ---- QK single pass (scores in log2 domain)
        float s[8][4];
#pragma unroll
        for (int nt = 0; nt < 8; nt++)
#pragma unroll
            for (int r = 0; r < 4; r++) s[nt][r] = 0.f;
#pragma unroll
        for (int c = 0; c < 8; c++) {
#pragma unroll
            for (int np = 0; np < 4; np++) {
                uint32_t bf[4];
                ldsm_x4(bf, bK + c * 32 + np * (16 * 272));
                mma_fp16(s[np * 2 + 0], qf[c], &bf[0]);
                mma_fp16(s[np * 2 + 1], qf[c], &bf[2]);
            }
        }

        // ---- causal mask (last tile only: j0 = qbase)
        if (t == ntiles - 1) {
            const int j0 = t * 64;
#pragma unroll
            for (int nt = 0; nt < 8; nt++)
#pragma unroll
                for (int r = 0; r < 4; r++) {
                    int grow2 = qbase + w * 16 + (lane >> 2) + (r >> 1) * 8;
                    int gcol = j0 + nt * 8 + (lane & 3) * 2 + (r & 1);
                    if (gcol > grow2) s[nt][r] = -1e9f;
                }
        }

        // ---- online softmax: p = 2^(s - mn) via ex2.approx.f16x2.
        uint32_t hp[2][8];
        float corr[2];
#pragma unroll
        for (int hh = 0; hh < 2; hh++) {
            float cm = -1e30f;
#pragma unroll
            for (int nt = 0; nt < 8; nt++)
                cm = fmaxf(cm, fmaxf(s[nt][hh * 2], s[nt][hh * 2 + 1]));
            cm = fmaxf(cm, __shfl_xor_sync(0xffffffffu, cm, 1));
            cm = fmaxf(cm, __shfl_xor_sync(0xffffffffu, cm, 2));
            float mn = fmaxf(m[hh], cm);
            corr[hh] = exp2f(m[hh] - mn);
            m[hh] = mn;
            float ps = 0.f;
#pragma unroll
            for (int nt = 0; nt < 8; nt++) {
                __half2 ha = __floats2half2_rn(s[nt][hh * 2] - mn,
                                               s[nt][hh * 2 + 1] - mn);
                uint32_t e = ex2_f16x2(*(uint32_t*)&ha);
                hp[hh][nt] = e;
                float2 pf = __half22float2(*(__half2*)&e);
                ps += pf.x + pf.y;
            }
            ps += __shfl_xor_sync(0xffffffffu, ps, 1);
            ps += __shfl_xor_sync(0xffffffffu, ps, 2);
            l[hh] = l[hh] * corr[hh] + ps;
        }
        // Lazy rescale: x1.0 is an exact identity, so skipping when every
        // lane has corr==1 is bit-identical to always multiplying.
        if (!__all_sync(0xffffffffu,
                        (corr[0] == 1.f) & (corr[1] == 1.f))) {
#pragma unroll
            for (int i = 0; i < 16; i++) {
                O[i][0] *= corr[0]; O[i][1] *= corr[0];
                O[i][2] *= corr[1]; O[i][3] *= corr[1];
            }
        }

        // ---- PV: P fragments direct from registers (no smem round-trip)
#pragma unroll
        for (int c = 0; c < 4; c++) {
            uint32_t a[4] = {hp[0][2 * c], hp[1][2 * c],
                             hp[0][2 * c + 1], hp[1][2 * c + 1]};
#pragma unroll
            for (int np = 0; np < 8; np++) {
                uint32_t bf[4];
                ldsm_x4(bf, bV + c * 32 + np * (16 * 144));
                mma_fp16(O[np * 2 + 0], a, &bf[0]);
                mma_fp16(O[np * 2 + 1], a, &bf[2]);
            }
        }

        __syncthreads();   // all warps done reading buf before overwrite
        if (t + 2 < ntiles) ISSUE_T(t + 2, buf);
        asm volatile("cp.async.commit_group;" ::: "memory");
    }

    // ---- epilogue: normalize, write fp16 activations [B,S,E]
    float inv0 = 1.f / l[0], inv1 = 1.f / l[1];
#pragma unroll
    for (int nt = 0; nt < 16; nt++) {
        int col = h * 128 + nt * 8 + (lane & 3) * 2;
#pragma unroll
        for (int hh = 0; hh < 2; hh++) {
            float inv = hh ? inv1 : inv0;
            int srow = qbase + w * 16 + (lane >> 2) + hh * 8;
            size_t rb = ((size_t)(b * Ss + srow)) * GK + col;
            *(__half2*)(g_a_p + rb) =
                __floats2half2_rn(O[nt][hh * 2] * inv, O[nt][hh * 2 + 1] * inv);
        }
    }
}

// ---------------------------------------------------------------------------
extern "C" void kernel_launch(void* const* d_in, const int* in_sizes, int n_in,
                              void* d_out, int out_size)
{
    const float* hidden = (const float*)d_in[0];
    const float* wqkv   = (const float*)d_in[1];
    const float* wout   = (const float*)d_in[2];
    float* out = (float*)d_out;

    __half *pap, *pwqkv, *pwout, *pqp, *pkp, *pvt;
    cudaGetSymbolAddress((void**)&pap,   g_a_p);
    cudaGetSymbolAddress((void**)&pwqkv, g_wqkv_p);
    cudaGetSymbolAddress((void**)&pwout, g_wout_p);
    cudaGetSymbolAddress((void**)&pqp,   g_qp);
    cudaGetSymbolAddress((void**)&pkp,   g_kp);
    cudaGetSymbolAddress((void**)&pvt,   g_vt);

    cudaFuncSetAttribute(gemm_mma<0>, cudaFuncAttributeMaxDynamicSharedMemorySize,
                         GEMM_SMEM_BYTES);
    cudaFuncSetAttribute(gemm_mma<1>, cudaFuncAttributeMaxDynamicSharedMemorySize,
                         GEMM_SMEM_BYTES);
    cudaFuncSetAttribute(attn9, cudaFuncAttributeMaxDynamicSharedMemorySize,
                         ATTN_SMEM);

    // 0) Fused prep: Wqkv pack + hidden pack + rope table (one launch)
    pack_all<<<2688, 256>>>(wqkv, hidden);
    // 1) QKV projection + fused rope/scale(log2e)/fp16 q,k,v^T epilogue
    {
        dim3 grid(3 * Ee / 128, Bb * Ss / 128);  // (48, 32)
        gemm_mma<1><<<grid, 256, GEMM_SMEM_BYTES>>>(pap, pwqkv, nullptr, 0);
    }
    // 2) Flash attention (reg-P, hoisted Q frags, lazy rescale, Wout pack)
    {
        dim3 grid(Ss / 64, Hh, Bb);  // (32,16,2)
        attn9<<<grid, 128, ATTN_SMEM>>>(pqp, pkp, pvt, wout);
    }
    // 3) Output projection
    {
        dim3 grid(Ee / 128, Bb * Ss / 128);  // (16, 32)
        gemm_mma<0><<<grid, 256, GEMM_SMEM_BYTES>>>(pap, pwout, out, Ee);
    }
}

// round 16
// speedup vs baseline: 1.5228x; 1.5228x over previous
#include <cuda_runtime.h>
#include <cuda_bf16.h>
#include <cuda_fp16.h>
#include <math.h>
#include <cstdint>

#define Bb 2
#define Ss 2048
#define Ee 2048
#define Hh 16
#define Dh 128
#define GK 2048          // fp16 single-pass: K = E
#define GKC64 32         // GK / 64 chunks

#define GSTAGE_BYTES 36864                      // (A 128 + B 128 rows) * 144 B
#define GEMM_SMEM_BYTES (3 * GSTAGE_BYTES)      // 110592 -> 2 CTAs/SM

// ---------------- scratch (__device__ globals; no allocation allowed) -------
__device__ __half g_a_p[(size_t)Bb * Ss * GK];        // fp16 activations
__device__ __half g_wqkv_p[(size_t)3 * Ee * GK];      // fp16 Wqkv
__device__ __half g_wout_p[(size_t)Ee * GK];          // fp16 Wout
__device__ __half g_qp[(size_t)Bb * Hh * Ss * Dh];    // q fp16, roped, scale*log2e
__device__ __half g_kp[(size_t)Bb * Hh * Ss * Dh];    // k fp16, roped
__device__ __half g_vt[(size_t)Bb * Hh * Dh * Ss];    // V^T fp16
__device__ float g_rope[(size_t)Ss * 16 * 2];         // (cos,sin) per (s, i)

__device__ __forceinline__ uint32_t smem_u32(const void* p) {
    uint32_t a;
    asm("{ .reg .u64 t; cvta.to.shared.u64 t, %1; cvt.u32.u64 %0, t; }"
        : "=r"(a) : "l"(p));
    return a;
}

// ---------------------------------------------------------------------------
// Fused prep kernel: blocks [0,1536) pack Wqkv (fp32->fp16, x8),
// blocks [1536,2560) pack hidden, blocks [2560,2688) build the rope table.
// ---------------------------------------------------------------------------
__global__ __launch_bounds__(256) void pack_all(
    const float* __restrict__ wqkv, const float* __restrict__ hidden)
{
    const int bid = blockIdx.x;
    if (bid < 1536) {
        int i0 = bid * 2048 + threadIdx.x;
#pragma unroll
        for (int t = 0; t < 8; t++) {
            int i = i0 + t * 256;
            float4 x = *(const float4*)(wqkv + (size_t)i * 4);
            *(__half2*)(g_wqkv_p + (size_t)i * 4) = __floats2half2_rn(x.x, x.y);
            *(__half2*)(g_wqkv_p + (size_t)i * 4 + 2) = __floats2half2_rn(x.z, x.w);
        }
    } else if (bid < 2560) {
        int i0 = (bid - 1536) * 2048 + threadIdx.x;
#pragma unroll
        for (int t = 0; t < 8; t++) {
            int i = i0 + t * 256;
            float4 x = *(const float4*)(hidden + (size_t)i * 4);
            *(__half2*)(g_a_p + (size_t)i * 4) = __floats2half2_rn(x.x, x.y);
            *(__half2*)(g_a_p + (size_t)i * 4 + 2) = __floats2half2_rn(x.z, x.w);
        }
    } else {
        int idx = (bid - 2560) * 256 + threadIdx.x;   // Ss*16 entries
        int i = idx & 15, s = idx >> 4;
        float f = powf(10000.f, -(float)i * 0.0625f);
        float sn, cs;
        sincosf((float)s * f, &sn, &cs);
        *(float2*)&g_rope[(size_t)idx * 2] = make_float2(cs, sn);
    }
}

// ---------------------------------------------------------------------------
// mma helpers
// ---------------------------------------------------------------------------
__device__ __forceinline__ void mma_fp16(float* c, const uint32_t* a, const uint32_t* b) {
    asm volatile(
        "mma.sync.aligned.m16n8k16.row.col.f32.f16.f16.f32 "
        "{%0,%1,%2,%3}, {%4,%5,%6,%7}, {%8,%9}, {%0,%1,%2,%3};"
        : "+f"(c[0]), "+f"(c[1]), "+f"(c[2]), "+f"(c[3])
        : "r"(a[0]), "r"(a[1]), "r"(a[2]), "r"(a[3]), "r"(b[0]), "r"(b[1]));
}
__device__ __forceinline__ void ldsm_x4(uint32_t* r, uint32_t addr) {
    asm volatile("ldmatrix.sync.aligned.m8n8.x4.shared.b16 {%0,%1,%2,%3}, [%4];"
        : "=r"(r[0]), "=r"(r[1]), "=r"(r[2]), "=r"(r[3]) : "r"(addr));
}
__device__ __forceinline__ uint32_t ex2_f16x2(uint32_t x) {
    uint32_t r;
    asm volatile("ex2.approx.f16x2 %0, %1;" : "=r"(r) : "r"(x));
    return r;
}

// ---------------------------------------------------------------------------
// fp16 GEMM (frozen shape): CTA 128x128, 8 warps (2M x 4N), warp 64x32,
// 256 threads, 2 CTAs/SM.  K-chunk 64, 3-stage cp.async, 144 B pitch.
// MODE 0: fp32 store.  MODE 1: QKV epilogue (rope table + fp16 q/k/v^T).
// ---------------------------------------------------------------------------
template <int MODE>
__global__ __launch_bounds__(256, 2) void gemm_mma(
    const __half* __restrict__ A, const __half* __restrict__ Bw,
    float* __restrict__ C, int Ncols)
{
    extern __shared__ __align__(16) uint32_t gsm[];
    const uint32_t sbase = smem_u32(gsm);

    const int tid = threadIdx.x;
    const int lane = tid & 31, w = tid >> 5;
    const int wm = w & 1, wn = w >> 1;
    const int mbase = blockIdx.y * 128, nbase = blockIdx.x * 128;

    float acc[4][4][4];
#pragma unroll
    for (int i = 0; i < 4; i++)
#pragma unroll
        for (int j = 0; j < 4; j++)
#pragma unroll
            for (int r = 0; r < 4; r++) acc[i][j][r] = 0.f;

    const int grow = tid >> 3, gseg = tid & 7;
    const __half* Ag = A + (size_t)(mbase + grow) * GK + gseg * 8;
    const __half* Bg = Bw + (size_t)(nbase + grow) * GK + gseg * 8;
    const size_t rstep32 = (size_t)32 * GK;
    const uint32_t dbase = grow * 144 + gseg * 16;

#define ISSUE(c, str) do {                                                     \
    uint32_t st = sbase + (uint32_t)(str) * GSTAGE_BYTES;                      \
    const __half* sA = Ag + (size_t)(c) * 64;                                  \
    const __half* sB = Bg + (size_t)(c) * 64;                                  \
    _Pragma("unroll")                                                          \
    for (int j = 0; j < 4; j++) {                                              \
        asm volatile("cp.async.cg.shared.global [%0], [%1], 16;"               \
            :: "r"(st + dbase + j * (32 * 144)), "l"(sA + j * rstep32));       \
        asm volatile("cp.async.cg.shared.global [%0], [%1], 16;"               \
            :: "r"(st + 18432 + dbase + j * (32 * 144)), "l"(sB + j * rstep32)); \
    }                                                                          \
} while (0)
#define COMMIT() asm volatile("cp.async.commit_group;" ::: "memory")
#define WAITG1() asm volatile("cp.async.wait_group 1;" ::: "memory")

    ISSUE(0, 0); COMMIT();
    ISSUE(1, 1); COMMIT();

    const int lane8 = lane & 7;
    const uint32_t aAddr = (uint32_t)((wm * 64 + ((lane >> 3) & 1) * 8 + lane8) * 144
                                      + (lane >> 4) * 16);
    const uint32_t bAddr = (uint32_t)(18432 + (wn * 32 + (lane >> 4) * 8 + lane8) * 144
                                      + ((lane >> 3) & 1) * 16);

    int str = 2, srd = 0;
    for (int c = 0; c < GKC64; c++) {
        WAITG1();
        __syncthreads();
        if (c + 2 < GKC64) ISSUE(c + 2, str);
        COMMIT();
        if (++str == 3) str = 0;

        const uint32_t st = sbase + (uint32_t)srd * GSTAGE_BYTES;
        if (++srd == 3) srd = 0;
#pragma unroll
        for (int ks = 0; ks < 4; ks++) {
            uint32_t a[4][4], b[2][4];
#pragma unroll
            for (int i = 0; i < 4; i++)
                ldsm_x4(a[i], st + aAddr + i * (16 * 144) + ks * 32);
#pragma unroll
            for (int jp = 0; jp < 2; jp++)
                ldsm_x4(b[jp], st + bAddr + jp * (16 * 144) + ks * 32);
#pragma unroll
            for (int i = 0; i < 4; i++)
#pragma unroll
                for (int j = 0; j < 4; j++)
                    mma_fp16(acc[i][j], a[i], &b[j >> 1][(j & 1) * 2]);
        }
    }

#pragma unroll
    for (int i = 0; i < 4; i++) {
        int m0 = mbase + wm * 64 + i * 16 + (lane >> 2);
#pragma unroll
        for (int j = 0; j < 4; j++) {
            int n0 = nbase + wn * 32 + j * 8 + (lane & 3) * 2;
            if constexpr (MODE == 0) {
                *(float2*)(C + (size_t)m0 * Ncols + n0) =
                    make_float2(acc[i][j][0], acc[i][j][1]);
                *(float2*)(C + (size_t)(m0 + 8) * Ncols + n0) =
                    make_float2(acc[i][j][2], acc[i][j][3]);
            } else {
                int mp = n0 / 768;
                int rr = n0 - mp * 768;
                int which = rr >> 8;
                int ccc = rr & 255;
                int hh = mp * 2 + (ccc >> 7);
                int dd = ccc & 127;
                int bb = m0 >> 11, ss = m0 & 2047;
                int bh2 = bb * Hh + hh;
                float v0 = acc[i][j][0], v1 = acc[i][j][1];
                float v2 = acc[i][j][2], v3 = acc[i][j][3];
                if (which == 2) {
                    size_t vb = ((size_t)bh2 * Dh + dd) * (size_t)Ss + ss;
                    g_vt[vb] = __float2half(v0);
                    g_vt[vb + Ss] = __float2half(v1);
                    g_vt[vb + 8] = __float2half(v2);
                    g_vt[vb + Ss + 8] = __float2half(v3);
                } else {
                    if (dd < 32) {
                        int ir = dd >> 1;
                        float2 cs1 = *(float2*)&g_rope[((size_t)ss * 16 + ir) * 2];
                        float2 cs2 = *(float2*)&g_rope[((size_t)(ss + 8) * 16 + ir) * 2];
                        float t0 = v0 * cs1.x - v1 * cs1.y;
                        v1 = v1 * cs1.x + v0 * cs1.y; v0 = t0;
                        t0 = v2 * cs2.x - v3 * cs2.y;
                        v3 = v3 * cs2.x + v2 * cs2.y; v2 = t0;
                    }
                    if (which == 0) {
                        // 1/sqrt(128) * log2(e): scores in log2 domain
                        const float sc = 0.08838834764831845f * 1.4426950408889634f;
                        v0 *= sc; v1 *= sc; v2 *= sc; v3 *= sc;
                    }
                    __half* P = (which == 0) ? g_qp : g_kp;
                    size_t rb = ((size_t)bh2 * Ss + ss) * Dh + dd;
                    *(__half2*)(P + rb) = __floats2half2_rn(v0, v1);
                    *(__half2*)(P + rb + 8 * Dh) = __floats2half2_rn(v2, v3);
                }
            }
        }
    }
}

// ---------------------------------------------------------------------------
// Flash attention v10 = R14's attn8 (register-resident P via the FA2 fragment
// identity; Q read per-tile via ldmatrix — NO hoisting, register budget is
// saturated) + zero-register warp-vote lazy O-rescale (x1.0 is an exact IEEE
// identity, so skipping when all lanes have corr==1 is bit-identical).
// smem: Qs 64x272 + 2x(Ks 64x272) + 2x(Vs 128x144) = 89088 B, 2 CTAs/SM.
// Wout fp32->fp16 pack fused in prologue.
// ---------------------------------------------------------------------------
#define ATTN_SMEM 89088

__global__ __launch_bounds__(128, 2) void attn10(
    const __half* __restrict__ qp, const __half* __restrict__ kp,
    const __half* __restrict__ vt, const float* __restrict__ wout_src)
{
    extern __shared__ char sm5[];
    const uint32_t sb = smem_u32(sm5);
    const uint32_t Qs = sb;              // 64*272 = 17408
    const uint32_t Ks0 = sb + 17408;     // + buf*17408 (2 bufs)
    const uint32_t Vs0 = sb + 52224;     // + buf*18432 (2 bufs)

    const int qb = (int)gridDim.x - 1 - (int)blockIdx.x;   // long blocks first
    const int h = blockIdx.y, b = blockIdx.z;
    const int bh = b * Hh + h;
    const int tid = threadIdx.x, lane = tid & 31, w = tid >> 5;
    const int qbase = qb * 64;
    const int ntiles = qb + 1;

    // Q tile: 64 rows x 128 halves
    {
        const __half* qg = qp + ((size_t)bh * Ss + qbase) * Dh;
#pragma unroll
        for (int t = 0; t < 8; t++) {
            int u = tid + t * 128;
            int r = u >> 4, sg = u & 15;
            asm volatile("cp.async.cg.shared.global [%0], [%1], 16;"
                :: "r"(Qs + r * 272 + sg * 16), "l"(qg + r * Dh + sg * 8));
        }
        asm volatile("cp.async.commit_group;" ::: "memory");
    }

#define ISSUE_T(tt, buf) do {                                                  \
    const __half* kg = kp + ((size_t)bh * Ss + (tt) * 64) * Dh;                \
    uint32_t kd = Ks0 + (buf) * 17408;                                         \
    _Pragma("unroll")                                                          \
    for (int t_ = 0; t_ < 8; t_++) {                                           \
        int u = tid + t_ * 128;                                                \
        int r = u >> 4, sg = u & 15;                                           \
        asm volatile("cp.async.cg.shared.global [%0], [%1], 16;"               \
            :: "r"(kd + r * 272 + sg * 16), "l"(kg + r * Dh + sg * 8));        \
    }                                                                          \
    const __half* vg = vt + (size_t)bh * Dh * Ss + (tt) * 64;                  \
    uint32_t vd = Vs0 + (buf) * 18432;                                         \
    _Pragma("unroll")                                                          \
    for (int t_ = 0; t_ < 8; t_++) {                                           \
        int u = tid + t_ * 128;                                                \
        int r = u >> 3, sg = u & 7;                                            \
        asm volatile("cp.async.cg.shared.global [%0], [%1], 16;"               \
            :: "r"(vd + r * 144 + sg * 16), "l"(vg + (size_t)r * Ss + sg * 8)); \
    }                                                                          \
} while (0)

    ISSUE_T(0, 0);
    asm volatile("cp.async.commit_group;" ::: "memory");
    if (ntiles > 1) ISSUE_T(1, 1);
    asm volatile("cp.async.commit_group;" ::: "memory");

    // ---- fused Wout pack: 1024 CTAs x 1024 float4 units (8 per thread).
    {
        int cta = (int)blockIdx.x + 32 * ((int)blockIdx.y + 16 * (int)blockIdx.z);
        int base = cta * 1024 + tid;
#pragma unroll
        for (int t = 0; t < 8; t++) {
            int i = base + t * 128;
            float4 x = *(const float4*)(wout_src + (size_t)i * 4);
            *(__half2*)(g_wout_p + (size_t)i * 4) = __floats2half2_rn(x.x, x.y);
            *(__half2*)(g_wout_p + (size_t)i * 4 + 2) = __floats2half2_rn(x.z, x.w);
        }
    }

    float O[16][4];
#pragma unroll
    for (int i = 0; i < 16; i++)
#pragma unroll
        for (int r = 0; r < 4; r++) O[i][r] = 0.f;
    float m[2] = {-1e30f, -1e30f}, l[2] = {0.f, 0.f};

    const uint32_t aQ = Qs + (w * 16 + (lane & 15)) * 272 + (lane >> 4) * 16;
    const int bRow = (lane >> 4) * 8 + (lane & 7);
    const int bCol = ((lane >> 3) & 1) * 16;

    for (int t = 0; t < ntiles; t++) {
        asm volatile("cp.async.wait_group 1;" ::: "memory");
        __syncthreads();
        const int buf = t & 1;
        const uint32_t bK = Ks0 + buf * 17408 + bRow * 272 + bCol;
        const uint32_t bV = Vs0 + buf * 18432 + bRow * 144 + bCol;

        // ---- QK single pass (scores in log2 domain)
        float s[8][4];
#pragma unroll
        for (int nt = 0; nt < 8; nt++)
#pragma unroll
            for (int r = 0; r < 4; r++) s[nt][r] = 0.f;
#pragma unroll
        for (int c = 0; c < 8; c++) {
            uint32_t a[4];
            ldsm_x4(a, aQ + c * 32);
#pragma unroll
            for (int np = 0; np < 4; np++) {
                uint32_t bf[4];
                ldsm_x4(bf, bK + c * 32 + np * (16 * 272));
                mma_fp16(s[np * 2 + 0], a, &bf[0]);
                mma_fp16(s[np * 2 + 1], a, &bf[2]);
            }
        }

        // ---- causal mask (last tile only: j0 = qbase)
        if (t == ntiles - 1) {
            const int j0 = t * 64;
#pragma unroll
            for (int nt = 0; nt < 8; nt++)
#pragma unroll
                for (int r = 0; r < 4; r++) {
                    int grow2 = qbase + w * 16 + (lane >> 2) + (r >> 1) * 8;
                    int gcol = j0 + nt * 8 + (lane & 3) * 2 + (r & 1);
                    if (gcol > grow2) s[nt][r] = -1e9f;
                }
        }

        // ---- online softmax: p = 2^(s - mn) via ex2.approx.f16x2.
        // hp[hh][nt] is the P fragment in exactly the PV A-operand layout.
        uint32_t hp[2][8];
        float corr[2];
#pragma unroll
        for (int hh = 0; hh < 2; hh++) {
            float cm = -1e30f;
#pragma unroll
            for (int nt = 0; nt < 8; nt++)
                cm = fmaxf(cm, fmaxf(s[nt][hh * 2], s[nt][hh * 2 + 1]));
            cm = fmaxf(cm, __shfl_xor_sync(0xffffffffu, cm, 1));
            cm = fmaxf(cm, __shfl_xor_sync(0xffffffffu, cm, 2));
            float mn = fmaxf(m[hh], cm);
            corr[hh] = exp2f(m[hh] - mn);
            m[hh] = mn;
            float ps = 0.f;
#pragma unroll
            for (int nt = 0; nt < 8; nt++) {
                __half2 ha = __floats2half2_rn(s[nt][hh * 2] - mn,
                                               s[nt][hh * 2 + 1] - mn);
                uint32_t e = ex2_f16x2(*(uint32_t*)&ha);
                hp[hh][nt] = e;
                float2 pf = __half22float2(*(__half2*)&e);
                ps += pf.x + pf.y;
            }
            ps += __shfl_xor_sync(0xffffffffu, ps, 1);
            ps += __shfl_xor_sync(0xffffffffu, ps, 2);
            l[hh] = l[hh] * corr[hh] + ps;
        }
        // Lazy rescale: x1.0 is an exact IEEE identity -> bit-identical skip.
        if (!__all_sync(0xffffffffu,
                        (corr[0] == 1.f) & (corr[1] == 1.f))) {
#pragma unroll
            for (int i = 0; i < 16; i++) {
                O[i][0] *= corr[0]; O[i][1] *= corr[0];
                O[i][2] *= corr[1]; O[i][3] *= corr[1];
            }
        }

        // ---- PV: P fragments direct from registers (no smem round-trip)
#pragma unroll
        for (int c = 0; c < 4; c++) {
            uint32_t a[4] = {hp[0][2 * c], hp[1][2 * c],
                             hp[0][2 * c + 1], hp[1][2 * c + 1]};
#pragma unroll
            for (int np = 0; np < 8; np++) {
                uint32_t bf[4];
                ldsm_x4(bf, bV + c * 32 + np * (16 * 144));
                mma_fp16(O[np * 2 + 0], a, &bf[0]);
                mma_fp16(O[np * 2 + 1], a, &bf[2]);
            }
        }

        __syncthreads();   // all warps done reading buf before overwrite
        if (t + 2 < ntiles) ISSUE_T(t + 2, buf);
        asm volatile("cp.async.commit_group;" ::: "memory");
    }

    // ---- epilogue: normalize, write fp16 activations [B,S,E]
    float inv0 = 1.f / l[0], inv1 = 1.f / l[1];
#pragma unroll
    for (int nt = 0; nt < 16; nt++) {
        int col = h * 128 + nt * 8 + (lane & 3) * 2;
#pragma unroll
        for (int hh = 0; hh < 2; hh++) {
            float inv = hh ? inv1 : inv0;
            int srow = qbase + w * 16 + (lane >> 2) + hh * 8;
            size_t rb = ((size_t)(b * Ss + srow)) * GK + col;
            *(__half2*)(g_a_p + rb) =
                __floats2half2_rn(O[nt][hh * 2] * inv, O[nt][hh * 2 + 1] * inv);
        }
    }
}

// ---------------------------------------------------------------------------
extern "C" void kernel_launch(void* const* d_in, const int* in_sizes, int n_in,
                              void* d_out, int out_size)
{
    const float* hidden = (const float*)d_in[0];
    const float* wqkv   = (const float*)d_in[1];
    const float* wout   = (const float*)d_in[2];
    float* out = (float*)d_out;

    __half *pap, *pwqkv, *pwout, *pqp, *pkp, *pvt;
    cudaGetSymbolAddress((void**)&pap,   g_a_p);
    cudaGetSymbolAddress((void**)&pwqkv, g_wqkv_p);
    cudaGetSymbolAddress((void**)&pwout, g_wout_p);
    cudaGetSymbolAddress((void**)&pqp,   g_qp);
    cudaGetSymbolAddress((void**)&pkp,   g_kp);
    cudaGetSymbolAddress((void**)&pvt,   g_vt);

    cudaFuncSetAttribute(gemm_mma<0>, cudaFuncAttributeMaxDynamicSharedMemorySize,
                         GEMM_SMEM_BYTES);
    cudaFuncSetAttribute(gemm_mma<1>, cudaFuncAttributeMaxDynamicSharedMemorySize,
                         GEMM_SMEM_BYTES);
    cudaFuncSetAttribute(attn10, cudaFuncAttributeMaxDynamicSharedMemorySize,
                         ATTN_SMEM);

    // 0) Fused prep: Wqkv pack + hidden pack + rope table (one launch)
    pack_all<<<2688, 256>>>(wqkv, hidden);
    // 1) QKV projection + fused rope/scale(log2e)/fp16 q,k,v^T epilogue
    {
        dim3 grid(3 * Ee / 128, Bb * Ss / 128);  // (48, 32)
        gemm_mma<1><<<grid, 256, GEMM_SMEM_BYTES>>>(pap, pwqkv, nullptr, 0);
    }
    // 2) Flash attention (reg-P, lazy rescale, fused Wout pack)
    {
        dim3 grid(Ss / 64, Hh, Bb);  // (32,16,2)
        attn10<<<grid, 128, ATTN_SMEM>>>(pqp, pkp, pvt, wout);
    }
    // 3) Output projection
    {
        dim3 grid(Ee / 128, Bb * Ss / 128);  // (16, 32)
        gemm_mma<0><<<grid, 256, GEMM_SMEM_BYTES>>>(pap, pwout, out, Ee);
    }
}

// round 17
// speedup vs baseline: 1.5238x; 1.0006x over previous
#include <cuda_runtime.h>
#include <cuda_bf16.h>
#include <cuda_fp16.h>
#include <math.h>
#include <cstdint>

#define Bb 2
#define Ss 2048
#define Ee 2048
#define Hh 16
#define Dh 128
#define GK 2048          // fp16 single-pass: K = E
#define GKC64 32         // GK / 64 chunks

#define GSTAGE_BYTES 36864                      // (A 128 + B 128 rows) * 144 B
#define GEMM_SMEM_BYTES (3 * GSTAGE_BYTES)      // 110592 -> 2 CTAs/SM

// ---------------- scratch (__device__ globals; no allocation allowed) -------
__device__ __half g_a_p[(size_t)Bb * Ss * GK];        // fp16 activations
__device__ __half g_wqkv_p[(size_t)3 * Ee * GK];      // fp16 Wqkv
__device__ __half g_wout_p[(size_t)Ee * GK];          // fp16 Wout
__device__ __half g_qp[(size_t)Bb * Hh * Ss * Dh];    // q fp16, roped, scale*log2e
__device__ __half g_kp[(size_t)Bb * Hh * Ss * Dh];    // k fp16, roped
__device__ __half g_vt[(size_t)Bb * Hh * Dh * Ss];    // V^T fp16
__device__ float g_rope[(size_t)Ss * 16 * 2];         // (cos,sin) per (s, i)

__device__ __forceinline__ uint32_t smem_u32(const void* p) {
    uint32_t a;
    asm("{ .reg .u64 t; cvta.to.shared.u64 t, %1; cvt.u32.u64 %0, t; }"
        : "=r"(a) : "l"(p));
    return a;
}

// Convert 8 fp32 (two float4) to 8 fp16 packed in a uint4 (one STG.128).
__device__ __forceinline__ uint4 cvt8_f32_f16(const float4 a, const float4 b) {
    __half2 h0 = __floats2half2_rn(a.x, a.y);
    __half2 h1 = __floats2half2_rn(a.z, a.w);
    __half2 h2 = __floats2half2_rn(b.x, b.y);
    __half2 h3 = __floats2half2_rn(b.z, b.w);
    uint4 r;
    r.x = *(uint32_t*)&h0; r.y = *(uint32_t*)&h1;
    r.z = *(uint32_t*)&h2; r.w = *(uint32_t*)&h3;
    return r;
}

// ---------------------------------------------------------------------------
// Fused prep kernel: blocks [0,1536) pack Wqkv, [1536,2560) pack hidden,
// [2560,2688) build the rope table.  Packs read 2x float4 and emit one
// STG.128 (8 halves) — wide-store streaming.
// ---------------------------------------------------------------------------
__global__ __launch_bounds__(256) void pack_all(
    const float* __restrict__ wqkv, const float* __restrict__ hidden)
{
    const int bid = blockIdx.x;
    if (bid < 1536) {
        // 3*2048*2048 halves = 1,572,864 groups of 8; 1536 blks x 256 thr x 4
        int u0 = bid * 1024 + threadIdx.x;
#pragma unroll
        for (int t = 0; t < 4; t++) {
            size_t u = (size_t)(u0 + t * 256);
            float4 a = *(const float4*)(wqkv + u * 8);
            float4 b = *(const float4*)(wqkv + u * 8 + 4);
            *(uint4*)(g_wqkv_p + u * 8) = cvt8_f32_f16(a, b);
        }
    } else if (bid < 2560) {
        // 2*2048*2048 halves = 1,048,576 groups of 8; 1024 blks x 256 x 4
        int u0 = (bid - 1536) * 1024 + threadIdx.x;
#pragma unroll
        for (int t = 0; t < 4; t++) {
            size_t u = (size_t)(u0 + t * 256);
            float4 a = *(const float4*)(hidden + u * 8);
            float4 b = *(const float4*)(hidden + u * 8 + 4);
            *(uint4*)(g_a_p + u * 8) = cvt8_f32_f16(a, b);
        }
    } else {
        int idx = (bid - 2560) * 256 + threadIdx.x;   // Ss*16 entries
        int i = idx & 15, s = idx >> 4;
        float f = powf(10000.f, -(float)i * 0.0625f);
        float sn, cs;
        sincosf((float)s * f, &sn, &cs);
        *(float2*)&g_rope[(size_t)idx * 2] = make_float2(cs, sn);
    }
}

// ---------------------------------------------------------------------------
// mma helpers
// ---------------------------------------------------------------------------
__device__ __forceinline__ void mma_fp16(float* c, const uint32_t* a, const uint32_t* b) {
    asm volatile(
        "mma.sync.aligned.m16n8k16.row.col.f32.f16.f16.f32 "
        "{%0,%1,%2,%3}, {%4,%5,%6,%7}, {%8,%9}, {%0,%1,%2,%3};"
        : "+f"(c[0]), "+f"(c[1]), "+f"(c[2]), "+f"(c[3])
        : "r"(a[0]), "r"(a[1]), "r"(a[2]), "r"(a[3]), "r"(b[0]), "r"(b[1]));
}
__device__ __forceinline__ void ldsm_x4(uint32_t* r, uint32_t addr) {
    asm volatile("ldmatrix.sync.aligned.m8n8.x4.shared.b16 {%0,%1,%2,%3}, [%4];"
        : "=r"(r[0]), "=r"(r[1]), "=r"(r[2]), "=r"(r[3]) : "r"(addr));
}
__device__ __forceinline__ uint32_t ex2_f16x2(uint32_t x) {
    uint32_t r;
    asm volatile("ex2.approx.f16x2 %0, %1;" : "=r"(r) : "r"(x));
    return r;
}

// ---------------------------------------------------------------------------
// fp16 GEMM (frozen shape): CTA 128x128, 8 warps (2M x 4N), warp 64x32,
// 256 threads, 2 CTAs/SM.  K-chunk 64, 3-stage cp.async, 144 B pitch.
// MODE 0: fp32 store.  MODE 1: QKV epilogue (rope table + fp16 q/k/v^T).
// ---------------------------------------------------------------------------
template <int MODE>
__global__ __launch_bounds__(256, 2) void gemm_mma(
    const __half* __restrict__ A, const __half* __restrict__ Bw,
    float* __restrict__ C, int Ncols)
{
    extern __shared__ __align__(16) uint32_t gsm[];
    const uint32_t sbase = smem_u32(gsm);

    const int tid = threadIdx.x;
    const int lane = tid & 31, w = tid >> 5;
    const int wm = w & 1, wn = w >> 1;
    const int mbase = blockIdx.y * 128, nbase = blockIdx.x * 128;

    float acc[4][4][4];
#pragma unroll
    for (int i = 0; i < 4; i++)
#pragma unroll
        for (int j = 0; j < 4; j++)
#pragma unroll
            for (int r = 0; r < 4; r++) acc[i][j][r] = 0.f;

    const int grow = tid >> 3, gseg = tid & 7;
    const __half* Ag = A + (size_t)(mbase + grow) * GK + gseg * 8;
    const __half* Bg = Bw + (size_t)(nbase + grow) * GK + gseg * 8;
    const size_t rstep32 = (size_t)32 * GK;
    const uint32_t dbase = grow * 144 + gseg * 16;

#define ISSUE(c, str) do {                                                     \
    uint32_t st = sbase + (uint32_t)(str) * GSTAGE_BYTES;                      \
    const __half* sA = Ag + (size_t)(c) * 64;                                  \
    const __half* sB = Bg + (size_t)(c) * 64;                                  \
    _Pragma("unroll")                                                          \
    for (int j = 0; j < 4; j++) {                                              \
        asm volatile("cp.async.cg.shared.global [%0], [%1], 16;"               \
            :: "r"(st + dbase + j * (32 * 144)), "l"(sA + j * rstep32));       \
        asm volatile("cp.async.cg.shared.global [%0], [%1], 16;"               \
            :: "r"(st + 18432 + dbase + j * (32 * 144)), "l"(sB + j * rstep32)); \
    }                                                                          \
} while (0)
#define COMMIT() asm volatile("cp.async.commit_group;" ::: "memory")
#define WAITG1() asm volatile("cp.async.wait_group 1;" ::: "memory")

    ISSUE(0, 0); COMMIT();
    ISSUE(1, 1); COMMIT();

    const int lane8 = lane & 7;
    const uint32_t aAddr = (uint32_t)((wm * 64 + ((lane >> 3) & 1) * 8 + lane8) * 144
                                      + (lane >> 4) * 16);
    const uint32_t bAddr = (uint32_t)(18432 + (wn * 32 + (lane >> 4) * 8 + lane8) * 144
                                      + ((lane >> 3) & 1) * 16);

    int str = 2, srd = 0;
    for (int c = 0; c < GKC64; c++) {
        WAITG1();
        __syncthreads();
        if (c + 2 < GKC64) ISSUE(c + 2, str);
        COMMIT();
        if (++str == 3) str = 0;

        const uint32_t st = sbase + (uint32_t)srd * GSTAGE_BYTES;
        if (++srd == 3) srd = 0;
#pragma unroll
        for (int ks = 0; ks < 4; ks++) {
            uint32_t a[4][4], b[2][4];
#pragma unroll
            for (int i = 0; i < 4; i++)
                ldsm_x4(a[i], st + aAddr + i * (16 * 144) + ks * 32);
#pragma unroll
            for (int jp = 0; jp < 2; jp++)
                ldsm_x4(b[jp], st + bAddr + jp * (16 * 144) + ks * 32);
#pragma unroll
            for (int i = 0; i < 4; i++)
#pragma unroll
                for (int j = 0; j < 4; j++)
                    mma_fp16(acc[i][j], a[i], &b[j >> 1][(j & 1) * 2]);
        }
    }

#pragma unroll
    for (int i = 0; i < 4; i++) {
        int m0 = mbase + wm * 64 + i * 16 + (lane >> 2);
#pragma unroll
        for (int j = 0; j < 4; j++) {
            int n0 = nbase + wn * 32 + j * 8 + (lane & 3) * 2;
            if constexpr (MODE == 0) {
                *(float2*)(C + (size_t)m0 * Ncols + n0) =
                    make_float2(acc[i][j][0], acc[i][j][1]);
                *(float2*)(C + (size_t)(m0 + 8) * Ncols + n0) =
                    make_float2(acc[i][j][2], acc[i][j][3]);
            } else {
                int mp = n0 / 768;
                int rr = n0 - mp * 768;
                int which = rr >> 8;
                int ccc = rr & 255;
                int hh = mp * 2 + (ccc >> 7);
                int dd = ccc & 127;
                int bb = m0 >> 11, ss = m0 & 2047;
                int bh2 = bb * Hh + hh;
                float v0 = acc[i][j][0], v1 = acc[i][j][1];
                float v2 = acc[i][j][2], v3 = acc[i][j][3];
                if (which == 2) {
                    size_t vb = ((size_t)bh2 * Dh + dd) * (size_t)Ss + ss;
                    g_vt[vb] = __float2half(v0);
                    g_vt[vb + Ss] = __float2half(v1);
                    g_vt[vb + 8] = __float2half(v2);
                    g_vt[vb + Ss + 8] = __float2half(v3);
                } else {
                    if (dd < 32) {
                        int ir = dd >> 1;
                        float2 cs1 = *(float2*)&g_rope[((size_t)ss * 16 + ir) * 2];
                        float2 cs2 = *(float2*)&g_rope[((size_t)(ss + 8) * 16 + ir) * 2];
                        float t0 = v0 * cs1.x - v1 * cs1.y;
                        v1 = v1 * cs1.x + v0 * cs1.y; v0 = t0;
                        t0 = v2 * cs2.x - v3 * cs2.y;
                        v3 = v3 * cs2.x + v2 * cs2.y; v2 = t0;
                    }
                    if (which == 0) {
                        // 1/sqrt(128) * log2(e): scores in log2 domain
                        const float sc = 0.08838834764831845f * 1.4426950408889634f;
                        v0 *= sc; v1 *= sc; v2 *= sc; v3 *= sc;
                    }
                    __half* P = (which == 0) ? g_qp : g_kp;
                    size_t rb = ((size_t)bh2 * Ss + ss) * Dh + dd;
                    *(__half2*)(P + rb) = __floats2half2_rn(v0, v1);
                    *(__half2*)(P + rb + 8 * Dh) = __floats2half2_rn(v2, v3);
                }
            }
        }
    }
}

// ---------------------------------------------------------------------------
// Flash attention v10 (frozen structure): register-resident P (FA2 fragment
// identity), per-tile Q ldmatrix (no hoisting — register budget saturated),
// zero-register warp-vote lazy O-rescale (bit-identical skip of x1.0).
// smem: Qs 64x272 + 2x(Ks 64x272) + 2x(Vs 128x144) = 89088 B, 2 CTAs/SM.
// Wout fp32->fp16 pack fused in prologue (wide-store version).
// ---------------------------------------------------------------------------
#define ATTN_SMEM 89088

__global__ __launch_bounds__(128, 2) void attn10(
    const __half* __restrict__ qp, const __half* __restrict__ kp,
    const __half* __restrict__ vt, const float* __restrict__ wout_src)
{
    extern __shared__ char sm5[];
    const uint32_t sb = smem_u32(sm5);
    const uint32_t Qs = sb;              // 64*272 = 17408
    const uint32_t Ks0 = sb + 17408;     // + buf*17408 (2 bufs)
    const uint32_t Vs0 = sb + 52224;     // + buf*18432 (2 bufs)

    const int qb = (int)gridDim.x - 1 - (int)blockIdx.x;   // long blocks first
    const int h = blockIdx.y, b = blockIdx.z;
    const int bh = b * Hh + h;
    const int tid = threadIdx.x, lane = tid & 31, w = tid >> 5;
    const int qbase = qb * 64;
    const int ntiles = qb + 1;

    // Q tile: 64 rows x 128 halves
    {
        const __half* qg = qp + ((size_t)bh * Ss + qbase) * Dh;
#pragma unroll
        for (int t = 0; t < 8; t++) {
            int u = tid + t * 128;
            int r = u >> 4, sg = u & 15;
            asm volatile("cp.async.cg.shared.global [%0], [%1], 16;"
                :: "r"(Qs + r * 272 + sg * 16), "l"(qg + r * Dh + sg * 8));
        }
        asm volatile("cp.async.commit_group;" ::: "memory");
    }

#define ISSUE_T(tt, buf) do {                                                  \
    const __half* kg = kp + ((size_t)bh * Ss + (tt) * 64) * Dh;                \
    uint32_t kd = Ks0 + (buf) * 17408;                                         \
    _Pragma("unroll")                                                          \
    for (int t_ = 0; t_ < 8; t_++) {                                           \
        int u = tid + t_ * 128;                                                \
        int r = u >> 4, sg = u & 15;                                           \
        asm volatile("cp.async.cg.shared.global [%0], [%1], 16;"               \
            :: "r"(kd + r * 272 + sg * 16), "l"(kg + r * Dh + sg * 8));        \
    }                                                                          \
    const __half* vg = vt + (size_t)bh * Dh * Ss + (tt) * 64;                  \
    uint32_t vd = Vs0 + (buf) * 18432;                                         \
    _Pragma("unroll")                                                          \
    for (int t_ = 0; t_ < 8; t_++) {                                           \
        int u = tid + t_ * 128;                                                \
        int r = u >> 3, sg = u & 7;                                            \
        asm volatile("cp.async.cg.shared.global [%0], [%1], 16;"               \
            :: "r"(vd + r * 144 + sg * 16), "l"(vg + (size_t)r * Ss + sg * 8)); \
    }                                                                          \
} while (0)

    ISSUE_T(0, 0);
    asm volatile("cp.async.commit_group;" ::: "memory");
    if (ntiles > 1) ISSUE_T(1, 1);
    asm volatile("cp.async.commit_group;" ::: "memory");

    // ---- fused Wout pack: 1024 CTAs x (128 thr x 4 units of 8 halves).
    {
        int cta = (int)blockIdx.x + 32 * ((int)blockIdx.y + 16 * (int)blockIdx.z);
        int u0 = cta * 512 + tid;
#pragma unroll
        for (int t = 0; t < 4; t++) {
            size_t u = (size_t)(u0 + t * 128);
            float4 a = *(const float4*)(wout_src + u * 8);
            float4 bq = *(const float4*)(wout_src + u * 8 + 4);
            *(uint4*)(g_wout_p + u * 8) = cvt8_f32_f16(a, bq);
        }
    }

    float O[16][4];
#pragma unroll
    for (int i = 0; i < 16; i++)
#pragma unroll
        for (int r = 0; r < 4; r++) O[i][r] = 0.f;
    float m[2] = {-1e30f, -1e30f}, l[2] = {0.f, 0.f};

    const uint32_t aQ = Qs + (w * 16 + (lane & 15)) * 272 + (lane >> 4) * 16;
    const int bRow = (lane >> 4) * 8 + (lane & 7);
    const int bCol = ((lane >> 3) & 1) * 16;

    for (int t = 0; t < ntiles; t++) {
        asm volatile("cp.async.wait_group 1;" ::: "memory");
        __syncthreads();
        const int buf = t & 1;
        const uint32_t bK = Ks0 + buf * 17408 + bRow * 272 + bCol;
        const uint32_t bV = Vs0 + buf * 18432 + bRow * 144 + bCol;

        // ---- QK single pass (scores in log2 domain)
        float s[8][4];
#pragma unroll
        for (int nt = 0; nt < 8; nt++)
#pragma unroll
            for (int r = 0; r < 4; r++) s[nt][r] = 0.f;
#pragma unroll
        for (int c = 0; c < 8; c++) {
            uint32_t a[4];
            ldsm_x4(a, aQ + c * 32);
#pragma unroll
            for (int np = 0; np < 4; np++) {
                uint32_t bf[4];
                ldsm_x4(bf, bK + c * 32 + np * (16 * 272));
                mma_fp16(s[np * 2 + 0], a, &bf[0]);
                mma_fp16(s[np * 2 + 1], a, &bf[2]);
            }
        }

        // ---- causal mask (last tile only: j0 = qbase)
        if (t == ntiles - 1) {
            const int j0 = t * 64;
#pragma unroll
            for (int nt = 0; nt < 8; nt++)
#pragma unroll
                for (int r = 0; r < 4; r++) {
                    int grow2 = qbase + w * 16 + (lane >> 2) + (r >> 1) * 8;
                    int gcol = j0 + nt * 8 + (lane & 3) * 2 + (r & 1);
                    if (gcol > grow2) s[nt][r] = -1e9f;
                }
        }

        // ---- online softmax: p = 2^(s - mn) via ex2.approx.f16x2.
        uint32_t hp[2][8];
        float corr[2];
#pragma unroll
        for (int hh = 0; hh < 2; hh++) {
            float cm = -1e30f;
#pragma unroll
            for (int nt = 0; nt < 8; nt++)
                cm = fmaxf(cm, fmaxf(s[nt][hh * 2], s[nt][hh * 2 + 1]));
            cm = fmaxf(cm, __shfl_xor_sync(0xffffffffu, cm, 1));
            cm = fmaxf(cm, __shfl_xor_sync(0xffffffffu, cm, 2));
            float mn = fmaxf(m[hh], cm);
            corr[hh] = exp2f(m[hh] - mn);
            m[hh] = mn;
            float ps = 0.f;
#pragma unroll
            for (int nt = 0; nt < 8; nt++) {
                __half2 ha = __floats2half2_rn(s[nt][hh * 2] - mn,
                                               s[nt][hh * 2 + 1] - mn);
                uint32_t e = ex2_f16x2(*(uint32_t*)&ha);
                hp[hh][nt] = e;
                float2 pf = __half22float2(*(__half2*)&e);
                ps += pf.x + pf.y;
            }
            ps += __shfl_xor_sync(0xffffffffu, ps, 1);
            ps += __shfl_xor_sync(0xffffffffu, ps, 2);
            l[hh] = l[hh] * corr[hh] + ps;
        }
        // Lazy rescale: x1.0 is an exact IEEE identity -> bit-identical skip.
        if (!__all_sync(0xffffffffu,
                        (corr[0] == 1.f) & (corr[1] == 1.f))) {
#pragma unroll
            for (int i = 0; i < 16; i++) {
                O[i][0] *= corr[0]; O[i][1] *= corr[0];
                O[i][2] *= corr[1]; O[i][3] *= corr[1];
            }
        }

        // ---- PV: P fragments direct from registers (no smem round-trip)
#pragma unroll
        for (int c = 0; c < 4; c++) {
            uint32_t a[4] = {hp[0][2 * c], hp[1][2 * c],
                             hp[0][2 * c + 1], hp[1][2 * c + 1]};
#pragma unroll
            for (int np = 0; np < 8; np++) {
                uint32_t bf[4];
                ldsm_x4(bf, bV + c * 32 + np * (16 * 144));
                mma_fp16(O[np * 2 + 0], a, &bf[0]);
                mma_fp16(O[np * 2 + 1], a, &bf[2]);
            }
        }

        __syncthreads();   // all warps done reading buf before overwrite
        if (t + 2 < ntiles) ISSUE_T(t + 2, buf);
        asm volatile("cp.async.commit_group;" ::: "memory");
    }

    // ---- epilogue: normalize, write fp16 activations [B,S,E]
    float inv0 = 1.f / l[0], inv1 = 1.f / l[1];
#pragma unroll
    for (int nt = 0; nt < 16; nt++) {
        int col = h * 128 + nt * 8 + (lane & 3) * 2;
#pragma unroll
        for (int hh = 0; hh < 2; hh++) {
            float inv = hh ? inv1 : inv0;
            int srow = qbase + w * 16 + (lane >> 2) + hh * 8;
            size_t rb = ((size_t)(b * Ss + srow)) * GK + col;
            *(__half2*)(g_a_p + rb) =
                __floats2half2_rn(O[nt][hh * 2] * inv, O[nt][hh * 2 + 1] * inv);
        }
    }
}

// ---------------------------------------------------------------------------
extern "C" void kernel_launch(void* const* d_in, const int* in_sizes, int n_in,
                              void* d_out, int out_size)
{
    const float* hidden = (const float*)d_in[0];
    const float* wqkv   = (const float*)d_in[1];
    const float* wout   = (const float*)d_in[2];
    float* out = (float*)d_out;

    __half *pap, *pwqkv, *pwout, *pqp, *pkp, *pvt;
    cudaGetSymbolAddress((void**)&pap,   g_a_p);
    cudaGetSymbolAddress((void**)&pwqkv, g_wqkv_p);
    cudaGetSymbolAddress((void**)&pwout, g_wout_p);
    cudaGetSymbolAddress((void**)&pqp,   g_qp);
    cudaGetSymbolAddress((void**)&pkp,   g_kp);
    cudaGetSymbolAddress((void**)&pvt,   g_vt);

    cudaFuncSetAttribute(gemm_mma<0>, cudaFuncAttributeMaxDynamicSharedMemorySize,
                         GEMM_SMEM_BYTES);
    cudaFuncSetAttribute(gemm_mma<1>, cudaFuncAttributeMaxDynamicSharedMemorySize,
                         GEMM_SMEM_BYTES);
    cudaFuncSetAttribute(attn10, cudaFuncAttributeMaxDynamicSharedMemorySize,
                         ATTN_SMEM);

    // 0) Fused prep: Wqkv pack + hidden pack + rope table (one launch)
    pack_all<<<2688, 256>>>(wqkv, hidden);
    // 1) QKV projection + fused rope/scale(log2e)/fp16 q,k,v^T epilogue
    {
        dim3 grid(3 * Ee / 128, Bb * Ss / 128);  // (48, 32)
        gemm_mma<1><<<grid, 256, GEMM_SMEM_BYTES>>>(pap, pwqkv, nullptr, 0);
    }
    // 2) Flash attention (reg-P, lazy rescale, fused Wout pack)
    {
        dim3 grid(Ss / 64, Hh, Bb);  // (32,16,2)
        attn10<<<grid, 128, ATTN_SMEM>>>(pqp, pkp, pvt, wout);
    }
    // 3) Output projection
    {
        dim3 grid(Ee / 128, Bb * Ss / 128);  // (16, 32)
        gemm_mma<0><<<grid, 256, GEMM_SMEM_BYTES>>>(pap, pwout, out, Ee);
    }
}